// round 5
// baseline (speedup 1.0000x reference)
#include <cuda_runtime.h>
#include <cuda_fp16.h>

// Problem constants
#define BB   4
#define CC   3
#define HH   1024
#define WW   1024
#define HWN  (HH * WW)          // 1<<20
#define NPIX (BB * HWN)         // 1<<22 = 4,194,304
#define NELEM (BB * CC * HWN)   // 12,582,912

#define EV_W 1024               // even-parity buffer row width (pixels)
#define OD_W 1026               // odd-parity buffer: +1 guard pixel each side

// fp16 accumulators, channel-last padded to 4 halves (8B) per pixel.
// Even buffer: pixel x at (row*EV_W + x)*4 halves  -> 16B aligned when x even.
// Odd buffer:  pixel x at (row*OD_W + x + 1)*4     -> 16B aligned when x odd.
// Every bilinear x-corner pair (x0, x0+1) is one 16B v4.f16x2 RED.
#define EV_HALVES ((size_t)BB * HH * EV_W * 4)
#define OD_HALVES ((size_t)BB * HH * OD_W * 4)
__device__ __align__(16) __half g_ev[2][EV_HALVES];
__device__ __align__(16) __half g_od[2][OD_HALVES];

__global__ void zero_kernel(float* __restrict__ out) {
    size_t i = (size_t)blockIdx.x * blockDim.x + threadIdx.x;
    const size_t nev4 = 2 * EV_HALVES / 8;   // float4 count
    const size_t nod4 = 2 * OD_HALVES / 8;
    float4* ev = reinterpret_cast<float4*>(&g_ev[0][0]);
    float4* od = reinterpret_cast<float4*>(&g_od[0][0]);
    const float4 z = make_float4(0.f, 0.f, 0.f, 0.f);
    if (i < nev4) ev[i] = z;
    if (i < nod4) od[i] = z;
    if (i == 0) *out = 0.f;
}

static __device__ __forceinline__ unsigned pack2(float a, float b) {
    __half2 h = __floats2half2_rn(a, b);
    return *reinterpret_cast<unsigned*>(&h);
}
static __device__ __forceinline__ void red_v4h(__half* p, unsigned a, unsigned b,
                                               unsigned c, unsigned d) {
    asm volatile("red.global.add.noftz.v4.f16x2 [%0], {%1, %2, %3, %4};"
                 :: "l"(p), "r"(a), "r"(b), "r"(c), "r"(d) : "memory");
}

// One thread per (f, b, h, w): f=0 warps im0 with flows[0]/t, f=1 warps im1
// with flows[1]/(1-t). Exactly one v4 RED per in-range corner row.
__global__ void splat_kernel(const float* __restrict__ flows,
                             const float* __restrict__ im0,
                             const float* __restrict__ im1,
                             const float* __restrict__ tval) {
    unsigned idx = blockIdx.x * blockDim.x + threadIdx.x;
    if (idx >= 2u * NPIX) return;
    const int      f   = idx >> 22;
    const unsigned rem = idx & (NPIX - 1);
    const int      b   = rem >> 20;
    const unsigned p   = rem & (HWN - 1);
    const int      h   = p >> 10;
    const int      w   = p & (WW - 1);

    const float t = tval[b];
    const float s = f ? (1.0f / (1.0f - t)) : (1.0f / t);

    const float* fb = flows + ((size_t)(f * BB + b) * 2) * HWN;
    const float X = (float)w + s * fb[p];
    const float Y = (float)h + s * fb[HWN + p];

    const float x0f = floorf(X), y0f = floorf(Y);
    const int   x0 = (int)x0f,  y0 = (int)y0f;
    const float fx = X - x0f,   fy = Y - y0f;

    if (x0 < -1 || x0 > WW - 1) return;      // no x corner in range
    if (y0 < -1 || y0 > HH - 1) return;      // no y corner in range

    const float* im = f ? im1 : im0;
    const float v0 = im[((size_t)b * CC + 0) * HWN + p];
    const float v1 = im[((size_t)b * CC + 1) * HWN + p];
    const float v2 = im[((size_t)b * CC + 2) * HWN + p];

    const bool odd = (x0 & 1) != 0;
    // per-row base pixel offset within the chosen buffer
    __half* buf  = odd ? g_od[f] : g_ev[f];
    const int rw = odd ? OD_W : EV_W;
    const int xo = odd ? (x0 + 1) : x0;

    #pragma unroll
    for (int r = 0; r < 2; r++) {
        const int y = y0 + r;
        if ((unsigned)y >= (unsigned)HH) continue;
        const float wy = r ? fy : (1.0f - fy);
        const float wa = (1.0f - fx) * wy;    // corner x0
        const float wb = fx * wy;             // corner x0+1
        __half* dst = buf + ((size_t)(b * HH + y) * rw + xo) * 4;
        red_v4h(dst,
                pack2(wa * v0, wa * v1), pack2(wa * v2, 0.0f),
                pack2(wb * v0, wb * v1), pack2(wb * v2, 0.0f));
    }
}

// loss = mean|warp0 - im1| + mean|warp1 - im0|  (each mean over NELEM)
__global__ void loss_kernel(const float* __restrict__ im0,
                            const float* __restrict__ im1,
                            float* __restrict__ out) {
    float acc = 0.f;
    const unsigned stride = gridDim.x * blockDim.x;
    for (unsigned i = blockIdx.x * blockDim.x + threadIdx.x; i < NPIX; i += stride) {
        const int      b = i >> 20;
        const unsigned p = i & (HWN - 1);
        const int      y = p >> 10;
        const int      x = p & (WW - 1);
        const size_t row = (size_t)(b * HH + y);
        const size_t ei = (row * EV_W + x) * 4;
        const size_t oi = (row * OD_W + x + 1) * 4;

        #pragma unroll
        for (int f = 0; f < 2; f++) {
            const uint2 ue = *reinterpret_cast<const uint2*>(&g_ev[f][ei]);
            const uint2 uo = *reinterpret_cast<const uint2*>(&g_od[f][oi]);
            const float2 ea = __half22float2(*reinterpret_cast<const __half2*>(&ue.x));
            const float2 eb = __half22float2(*reinterpret_cast<const __half2*>(&ue.y));
            const float2 oa = __half22float2(*reinterpret_cast<const __half2*>(&uo.x));
            const float2 ob = __half22float2(*reinterpret_cast<const __half2*>(&uo.y));
            const float c0 = ea.x + oa.x;
            const float c1 = ea.y + oa.y;
            const float c2 = eb.x + ob.x;
            const float* ref = f ? im0 : im1;   // warp0 vs im1, warp1 vs im0
            const size_t base = (size_t)b * CC * HWN + p;
            acc += fabsf(c0 - ref[base]) +
                   fabsf(c1 - ref[base + HWN]) +
                   fabsf(c2 - ref[base + 2 * HWN]);
        }
    }
    // intra-warp reduce
    #pragma unroll
    for (int o = 16; o; o >>= 1) acc += __shfl_down_sync(0xffffffffu, acc, o);
    __shared__ float sb[32];
    const int lane = threadIdx.x & 31, wid = threadIdx.x >> 5;
    if (lane == 0) sb[wid] = acc;
    __syncthreads();
    if (wid == 0) {
        acc = (lane < (int)(blockDim.x >> 5)) ? sb[lane] : 0.f;
        #pragma unroll
        for (int o = 16; o; o >>= 1) acc += __shfl_down_sync(0xffffffffu, acc, o);
        if (lane == 0) atomicAdd(out, acc * (1.0f / (float)NELEM));
    }
}

extern "C" void kernel_launch(void* const* d_in, const int* in_sizes, int n_in,
                              void* d_out, int out_size) {
    const float* flows = (const float*)d_in[0];   // [2,B,2,H,W]
    const float* im0   = (const float*)d_in[1];   // [B,C,H,W]
    const float* im1   = (const float*)d_in[2];   // [B,C,H,W]
    const float* tval  = (const float*)d_in[3];   // [B]
    float* out = (float*)d_out;

    {
        const size_t n4 = 2 * OD_HALVES / 8;      // odd is the larger region
        const int threads = 256;
        const int blocks = (int)((n4 + threads - 1) / threads);
        zero_kernel<<<blocks, threads>>>(out);
    }
    {
        const int threads = 256;
        const int blocks = (2 * NPIX + threads - 1) / threads;  // 32768
        splat_kernel<<<blocks, threads>>>(flows, im0, im1, tval);
    }
    {
        const int threads = 256;
        const int blocks = 148 * 16;   // grid-stride over 4M pixels
        loss_kernel<<<blocks, threads>>>(im0, im1, out);
    }
}

// round 6
// speedup vs baseline: 1.0011x; 1.0011x over previous
#include <cuda_runtime.h>
#include <cuda_fp16.h>

// Problem constants
#define BB   4
#define CC   3
#define HH   1024
#define WW   1024
#define HWN  (HH * WW)          // 1<<20
#define NPIX (BB * HWN)         // 1<<22 = 4,194,304
#define NELEM (BB * CC * HWN)   // 12,582,912

#define EV_W 1024               // even-parity buffer row width (pixels)
#define OD_W 1026               // odd-parity buffer: +1 guard pixel each side

// fp16 accumulators, channel-last padded to 4 halves (8B) per pixel.
// Even buffer: pixel x at (row*EV_W + x)*4 halves  -> 16B aligned when x even.
// Odd buffer:  pixel x at (row*OD_W + x + 1)*4     -> 16B aligned when x odd.
// Every bilinear x-corner pair (x0, x0+1) is one 16B v4.f16x2 RED.
#define EV_HALVES ((size_t)BB * HH * EV_W * 4)
#define OD_HALVES ((size_t)BB * HH * OD_W * 4)
__device__ __align__(16) __half g_ev[2][EV_HALVES];
__device__ __align__(16) __half g_od[2][OD_HALVES];

static __device__ __forceinline__ unsigned pack2(float a, float b) {
    __half2 h = __floats2half2_rn(a, b);
    return *reinterpret_cast<unsigned*>(&h);
}
static __device__ __forceinline__ void red_v4h(__half* p, unsigned a, unsigned b,
                                               unsigned c, unsigned d) {
    asm volatile("red.global.add.noftz.v4.f16x2 [%0], {%1, %2, %3, %4};"
                 :: "l"(p), "r"(a), "r"(b), "r"(c), "r"(d) : "memory");
}

// One thread per (f, b, h, w): f=0 warps im0 with flows[0]/t, f=1 warps im1
// with flows[1]/(1-t). Exactly one v4 RED per in-range corner row.
__global__ void splat_kernel(const float* __restrict__ flows,
                             const float* __restrict__ im0,
                             const float* __restrict__ im1,
                             const float* __restrict__ tval) {
    unsigned idx = blockIdx.x * blockDim.x + threadIdx.x;
    const int      f   = idx >> 22;
    const unsigned rem = idx & (NPIX - 1);
    const int      b   = rem >> 20;
    const unsigned p   = rem & (HWN - 1);
    const int      h   = p >> 10;
    const int      w   = p & (WW - 1);

    const float t = tval[b];
    const float s = f ? (1.0f / (1.0f - t)) : (1.0f / t);

    const float* fb = flows + ((size_t)(f * BB + b) * 2) * HWN;
    const float X = (float)w + s * fb[p];
    const float Y = (float)h + s * fb[HWN + p];

    const float x0f = floorf(X), y0f = floorf(Y);
    const int   x0 = (int)x0f,  y0 = (int)y0f;
    const float fx = X - x0f,   fy = Y - y0f;

    if (x0 < -1 || x0 > WW - 1) return;      // no x corner in range
    if (y0 < -1 || y0 > HH - 1) return;      // no y corner in range

    const float* im = f ? im1 : im0;
    const float v0 = im[((size_t)b * CC + 0) * HWN + p];
    const float v1 = im[((size_t)b * CC + 1) * HWN + p];
    const float v2 = im[((size_t)b * CC + 2) * HWN + p];

    const bool odd = (x0 & 1) != 0;
    __half* buf  = odd ? g_od[f] : g_ev[f];
    const int rw = odd ? OD_W : EV_W;
    const int xo = odd ? (x0 + 1) : x0;

    #pragma unroll
    for (int r = 0; r < 2; r++) {
        const int y = y0 + r;
        if ((unsigned)y >= (unsigned)HH) continue;
        const float wy = r ? fy : (1.0f - fy);
        const float wa = (1.0f - fx) * wy;    // corner x0
        const float wb = fx * wy;             // corner x0+1
        __half* dst = buf + ((size_t)(b * HH + y) * rw + xo) * 4;
        red_v4h(dst,
                pack2(wa * v0, wa * v1), pack2(wa * v2, 0.0f),
                pack2(wb * v0, wb * v1), pack2(wb * v2, 0.0f));
    }
}

// loss = mean|warp0 - im1| + mean|warp1 - im0|, 2 pixels per thread.
__global__ void loss_kernel(const float* __restrict__ im0,
                            const float* __restrict__ im1,
                            float* __restrict__ out) {
    float acc = 0.f;
    const unsigned stride = gridDim.x * blockDim.x;
    const unsigned NPAIR = NPIX / 2;
    for (unsigned i = blockIdx.x * blockDim.x + threadIdx.x; i < NPAIR; i += stride) {
        const unsigned pp = i << 1;               // first pixel of the pair
        const int      b  = pp >> 20;
        const unsigned p  = pp & (HWN - 1);
        const int      y  = p >> 10;
        const int      x  = p & (WW - 1);         // even
        const size_t row = (size_t)(b * HH + y);
        const size_t ei = (row * EV_W + x) * 4;       // 16B aligned
        const size_t oi = (row * OD_W + x + 1) * 4;   // 8B aligned

        #pragma unroll
        for (int f = 0; f < 2; f++) {
            const uint4 ue = *reinterpret_cast<const uint4*>(&g_ev[f][ei]);
            const uint2 uoA = *reinterpret_cast<const uint2*>(&g_od[f][oi]);
            const uint2 uoB = *reinterpret_cast<const uint2*>(&g_od[f][oi + 4]);
            const float2 e0a = __half22float2(*reinterpret_cast<const __half2*>(&ue.x));
            const float2 e0b = __half22float2(*reinterpret_cast<const __half2*>(&ue.y));
            const float2 e1a = __half22float2(*reinterpret_cast<const __half2*>(&ue.z));
            const float2 e1b = __half22float2(*reinterpret_cast<const __half2*>(&ue.w));
            const float2 o0a = __half22float2(*reinterpret_cast<const __half2*>(&uoA.x));
            const float2 o0b = __half22float2(*reinterpret_cast<const __half2*>(&uoA.y));
            const float2 o1a = __half22float2(*reinterpret_cast<const __half2*>(&uoB.x));
            const float2 o1b = __half22float2(*reinterpret_cast<const __half2*>(&uoB.y));

            const float* ref = f ? im0 : im1;     // warp0 vs im1, warp1 vs im0
            const size_t base = (size_t)b * CC * HWN + p;
            const float2 r0 = *reinterpret_cast<const float2*>(&ref[base]);
            const float2 r1 = *reinterpret_cast<const float2*>(&ref[base + HWN]);
            const float2 r2 = *reinterpret_cast<const float2*>(&ref[base + 2 * HWN]);

            acc += fabsf(e0a.x + o0a.x - r0.x) +
                   fabsf(e0a.y + o0a.y - r1.x) +
                   fabsf(e0b.x + o0b.x - r2.x);
            acc += fabsf(e1a.x + o1a.x - r0.y) +
                   fabsf(e1a.y + o1a.y - r1.y) +
                   fabsf(e1b.x + o1b.x - r2.y);
        }
    }
    // intra-warp reduce
    #pragma unroll
    for (int o = 16; o; o >>= 1) acc += __shfl_down_sync(0xffffffffu, acc, o);
    __shared__ float sb[32];
    const int lane = threadIdx.x & 31, wid = threadIdx.x >> 5;
    if (lane == 0) sb[wid] = acc;
    __syncthreads();
    if (wid == 0) {
        acc = (lane < (int)(blockDim.x >> 5)) ? sb[lane] : 0.f;
        #pragma unroll
        for (int o = 16; o; o >>= 1) acc += __shfl_down_sync(0xffffffffu, acc, o);
        if (lane == 0) atomicAdd(out, acc * (1.0f / (float)NELEM));
    }
}

extern "C" void kernel_launch(void* const* d_in, const int* in_sizes, int n_in,
                              void* d_out, int out_size) {
    const float* flows = (const float*)d_in[0];   // [2,B,2,H,W]
    const float* im0   = (const float*)d_in[1];   // [B,C,H,W]
    const float* im1   = (const float*)d_in[2];   // [B,C,H,W]
    const float* tval  = (const float*)d_in[3];   // [B]
    float* out = (float*)d_out;

    // Zero accumulators + output via memset nodes (graph-capturable).
    void* ev_ptr = nullptr;
    void* od_ptr = nullptr;
    cudaGetSymbolAddress(&ev_ptr, g_ev);
    cudaGetSymbolAddress(&od_ptr, g_od);
    cudaMemsetAsync(ev_ptr, 0, sizeof(g_ev));
    cudaMemsetAsync(od_ptr, 0, sizeof(g_od));
    cudaMemsetAsync(out, 0, sizeof(float));

    {
        const int threads = 256;
        const int blocks = (2 * NPIX) / threads;  // 32768, exact
        splat_kernel<<<blocks, threads>>>(flows, im0, im1, tval);
    }
    {
        const int threads = 256;
        const int blocks = 148 * 24;   // grid-stride over 2M pixel-pairs
        loss_kernel<<<blocks, threads>>>(im0, im1, out);
    }
}

// round 7
// speedup vs baseline: 1.0083x; 1.0072x over previous
#include <cuda_runtime.h>
#include <cuda_fp16.h>

// Problem constants
#define BB   4
#define CC   3
#define HH   1024
#define WW   1024
#define HWN  (HH * WW)          // 1<<20
#define NPIX (BB * HWN)         // 1<<22 = 4,194,304
#define NELEM (BB * CC * HWN)   // 12,582,912
#define NPAIR (NPIX / 2)        // 2,097,152 even-x pixel pairs

#define EV_W 1024               // even-parity buffer row width (pixels)
#define OD_W 1026               // odd-parity buffer: +1 guard pixel each side

// fp16 accumulators, channel-last padded to 4 halves (8B) per pixel.
// Even buffer: pixel x at (row*EV_W + x)*4 halves  -> 16B aligned when x even.
// Odd buffer:  pixel x at (row*OD_W + x + 1)*4     -> 16B aligned when x odd.
// Every bilinear x-corner pair (x0, x0+1) is one 16B v4.f16x2 RED.
#define EV_HALVES ((size_t)BB * HH * EV_W * 4)
#define OD_HALVES ((size_t)BB * HH * OD_W * 4)
__device__ __align__(16) __half g_ev[2][EV_HALVES];
__device__ __align__(16) __half g_od[2][OD_HALVES];

#define SPLAT_TPB   256
#define SPLAT_BLKS  (NPIX / SPLAT_TPB)        // 16384 per f
#define ZBLK        2368                       // zero-role blocks (148*16)
#define LBLK        1776                       // loss-role blocks (148*12)

static __device__ __forceinline__ unsigned pack2(float a, float b) {
    __half2 h = __floats2half2_rn(a, b);
    return *reinterpret_cast<unsigned*>(&h);
}
static __device__ __forceinline__ void red_v4h(__half* p, unsigned a, unsigned b,
                                               unsigned c, unsigned d) {
    asm volatile("red.global.add.noftz.v4.f16x2 [%0], {%1, %2, %3, %4};"
                 :: "l"(p), "r"(a), "r"(b), "r"(c), "r"(d) : "memory");
}

// ---------- role bodies ----------

// Zero buffers of one f (grid-stride over float4s), role-local block index.
static __device__ __forceinline__ void zero_f_dev(int f, unsigned rb, unsigned nblk) {
    const unsigned tidg = rb * SPLAT_TPB + threadIdx.x;
    const unsigned stride = nblk * SPLAT_TPB;
    float4* ev = reinterpret_cast<float4*>(&g_ev[f][0]);
    float4* od = reinterpret_cast<float4*>(&g_od[f][0]);
    const float4 z = make_float4(0.f, 0.f, 0.f, 0.f);
    const size_t nev = EV_HALVES / 8, nod = OD_HALVES / 8;
    for (size_t i = tidg; i < nev; i += stride) ev[i] = z;
    for (size_t i = tidg; i < nod; i += stride) od[i] = z;
}

// Splat one source pixel of warp f. r in [0, NPIX).
static __device__ __forceinline__ void splat_dev(const float* __restrict__ flows,
                                                 const float* __restrict__ im0,
                                                 const float* __restrict__ im1,
                                                 const float* __restrict__ tval,
                                                 int f, unsigned r) {
    const int      b = r >> 20;
    const unsigned p = r & (HWN - 1);
    const int      h = p >> 10;
    const int      w = p & (WW - 1);

    const float t = tval[b];
    const float s = f ? (1.0f / (1.0f - t)) : (1.0f / t);

    const float* fb = flows + ((size_t)(f * BB + b) * 2) * HWN;
    const float X = (float)w + s * fb[p];
    const float Y = (float)h + s * fb[HWN + p];

    const float x0f = floorf(X), y0f = floorf(Y);
    const int   x0 = (int)x0f,  y0 = (int)y0f;
    const float fx = X - x0f,   fy = Y - y0f;

    if (x0 < -1 || x0 > WW - 1) return;
    if (y0 < -1 || y0 > HH - 1) return;

    const float* im = f ? im1 : im0;
    const float v0 = im[((size_t)b * CC + 0) * HWN + p];
    const float v1 = im[((size_t)b * CC + 1) * HWN + p];
    const float v2 = im[((size_t)b * CC + 2) * HWN + p];

    const bool odd = (x0 & 1) != 0;
    __half* buf  = odd ? g_od[f] : g_ev[f];
    const int rw = odd ? OD_W : EV_W;
    const int xo = odd ? (x0 + 1) : x0;

    #pragma unroll
    for (int rr = 0; rr < 2; rr++) {
        const int y = y0 + rr;
        if ((unsigned)y >= (unsigned)HH) continue;
        const float wy = rr ? fy : (1.0f - fy);
        const float wa = (1.0f - fx) * wy;
        const float wb = fx * wy;
        __half* dst = buf + ((size_t)(b * HH + y) * rw + xo) * 4;
        red_v4h(dst,
                pack2(wa * v0, wa * v1), pack2(wa * v2, 0.0f),
                pack2(wb * v0, wb * v1), pack2(wb * v2, 0.0f));
    }
}

// Partial loss for one f: sum |warp_f - ref| over all pixels (2 px/thread),
// block-reduce, atomicAdd scaled term into out. rb = role-local block index.
static __device__ __forceinline__ void loss_dev(const float* __restrict__ ref,
                                                int f, unsigned rb, unsigned nblk,
                                                float* __restrict__ out) {
    float acc = 0.f;
    const unsigned stride = nblk * SPLAT_TPB;
    for (unsigned i = rb * SPLAT_TPB + threadIdx.x; i < NPAIR; i += stride) {
        const unsigned pp = i << 1;
        const int      b  = pp >> 20;
        const unsigned p  = pp & (HWN - 1);
        const int      y  = p >> 10;
        const int      x  = p & (WW - 1);          // even
        const size_t row = (size_t)(b * HH + y);
        const size_t ei = (row * EV_W + x) * 4;
        const size_t oi = (row * OD_W + x + 1) * 4;

        const uint4 ue  = *reinterpret_cast<const uint4*>(&g_ev[f][ei]);
        const uint2 uoA = *reinterpret_cast<const uint2*>(&g_od[f][oi]);
        const uint2 uoB = *reinterpret_cast<const uint2*>(&g_od[f][oi + 4]);
        const float2 e0a = __half22float2(*reinterpret_cast<const __half2*>(&ue.x));
        const float2 e0b = __half22float2(*reinterpret_cast<const __half2*>(&ue.y));
        const float2 e1a = __half22float2(*reinterpret_cast<const __half2*>(&ue.z));
        const float2 e1b = __half22float2(*reinterpret_cast<const __half2*>(&ue.w));
        const float2 o0a = __half22float2(*reinterpret_cast<const __half2*>(&uoA.x));
        const float2 o0b = __half22float2(*reinterpret_cast<const __half2*>(&uoA.y));
        const float2 o1a = __half22float2(*reinterpret_cast<const __half2*>(&uoB.x));
        const float2 o1b = __half22float2(*reinterpret_cast<const __half2*>(&uoB.y));

        const size_t base = (size_t)b * CC * HWN + p;
        const float2 r0 = *reinterpret_cast<const float2*>(&ref[base]);
        const float2 r1 = *reinterpret_cast<const float2*>(&ref[base + HWN]);
        const float2 r2 = *reinterpret_cast<const float2*>(&ref[base + 2 * HWN]);

        acc += fabsf(e0a.x + o0a.x - r0.x) +
               fabsf(e0a.y + o0a.y - r1.x) +
               fabsf(e0b.x + o0b.x - r2.x);
        acc += fabsf(e1a.x + o1a.x - r0.y) +
               fabsf(e1a.y + o1a.y - r1.y) +
               fabsf(e1b.x + o1b.x - r2.y);
    }
    #pragma unroll
    for (int o = 16; o; o >>= 1) acc += __shfl_down_sync(0xffffffffu, acc, o);
    __shared__ float sb[8];
    const int lane = threadIdx.x & 31, wid = threadIdx.x >> 5;
    if (lane == 0) sb[wid] = acc;
    __syncthreads();
    if (wid == 0) {
        acc = (lane < (SPLAT_TPB >> 5)) ? sb[lane] : 0.f;
        #pragma unroll
        for (int o = 16; o; o >>= 1) acc += __shfl_down_sync(0xffffffffu, acc, o);
        if (lane == 0) atomicAdd(out, acc * (1.0f / (float)NELEM));
    }
}

// ---------- kernels ----------

// k1: zero f0 buffers + out
__global__ void k1_zero0(float* __restrict__ out) {
    zero_f_dev(0, blockIdx.x, gridDim.x);
    if (blockIdx.x == 0 && threadIdx.x == 0) *out = 0.f;
}

// k2: zero f1 buffers (blocks [0,ZBLK)) || splat f0 (rest)
__global__ void k2_zero1_splat0(const float* __restrict__ flows,
                                const float* __restrict__ im0,
                                const float* __restrict__ im1,
                                const float* __restrict__ tval) {
    if (blockIdx.x < ZBLK) {
        zero_f_dev(1, blockIdx.x, ZBLK);
    } else {
        const unsigned r = (blockIdx.x - ZBLK) * SPLAT_TPB + threadIdx.x;
        splat_dev(flows, im0, im1, tval, 0, r);
    }
}

// k3: loss f0 (blocks [0,LBLK)) || splat f1 (rest)
__global__ void k3_loss0_splat1(const float* __restrict__ flows,
                                const float* __restrict__ im0,
                                const float* __restrict__ im1,
                                const float* __restrict__ tval,
                                float* __restrict__ out) {
    if (blockIdx.x < LBLK) {
        loss_dev(im1, 0, blockIdx.x, LBLK, out);   // warp0 vs im1
    } else {
        const unsigned r = (blockIdx.x - LBLK) * SPLAT_TPB + threadIdx.x;
        splat_dev(flows, im0, im1, tval, 1, r);
    }
}

// k4: loss f1
__global__ void k4_loss1(const float* __restrict__ im0, float* __restrict__ out) {
    loss_dev(im0, 1, blockIdx.x, gridDim.x, out);  // warp1 vs im0
}

extern "C" void kernel_launch(void* const* d_in, const int* in_sizes, int n_in,
                              void* d_out, int out_size) {
    const float* flows = (const float*)d_in[0];   // [2,B,2,H,W]
    const float* im0   = (const float*)d_in[1];   // [B,C,H,W]
    const float* im1   = (const float*)d_in[2];   // [B,C,H,W]
    const float* tval  = (const float*)d_in[3];   // [B]
    float* out = (float*)d_out;

    k1_zero0<<<ZBLK, SPLAT_TPB>>>(out);
    k2_zero1_splat0<<<ZBLK + SPLAT_BLKS, SPLAT_TPB>>>(flows, im0, im1, tval);
    k3_loss0_splat1<<<LBLK + SPLAT_BLKS, SPLAT_TPB>>>(flows, im0, im1, tval, out);
    k4_loss1<<<LBLK, SPLAT_TPB>>>(im0, out);
}

// round 8
// speedup vs baseline: 1.1298x; 1.1205x over previous
#include <cuda_runtime.h>
#include <cuda_fp16.h>

// Problem constants
#define BB   4
#define CC   3
#define HH   1024
#define WW   1024
#define SW   (WW + 4)           // acc row stride in pixels: 2 guard cols each side
#define HWN  (HH * WW)          // 1<<20
#define NPIX (BB * HWN)         // 1<<22
#define NELEM (BB * CC * HWN)   // 12,582,912
#define NPAIR (NPIX / 2)

// Single fp16 accumulator per f: channel-last padded [B,H,SW,4] (8B/pixel).
// 33.7 MB per f, 67.4 MB total -> fits the 126 MB L2.
#define ACC_HALVES ((size_t)BB * HH * SW * 4)
__device__ __align__(16) __half g_acc[2][ACC_HALVES];

#define TPB        256
#define SPLAT_BLKS (NPIX / TPB)   // 16384 per f
#define ZBLK       1184           // zero-role blocks (148*8)
#define LBLK       1184           // loss-role blocks (148*8)

static __device__ __forceinline__ unsigned pack2(float a, float b) {
    __half2 h = __floats2half2_rn(a, b);
    return *reinterpret_cast<unsigned*>(&h);
}
static __device__ __forceinline__ void red_v4h(__half* p, unsigned a, unsigned b,
                                               unsigned c, unsigned d) {
    asm volatile("red.global.add.noftz.v4.f16x2 [%0], {%1, %2, %3, %4};"
                 :: "l"(p), "r"(a), "r"(b), "r"(c), "r"(d) : "memory");
}
static __device__ __forceinline__ void red_v2h(__half* p, unsigned a, unsigned b) {
    asm volatile("red.global.add.noftz.v2.f16x2 [%0], {%1, %2};"
                 :: "l"(p), "r"(a), "r"(b) : "memory");
}

// ---------- role bodies ----------

// Zero accumulator of one f (grid-stride float4 streaming stores).
static __device__ __forceinline__ void zero_f_dev(int f, unsigned rb, unsigned nblk) {
    const unsigned tidg = rb * TPB + threadIdx.x;
    const unsigned stride = nblk * TPB;
    float4* a = reinterpret_cast<float4*>(&g_acc[f][0]);
    const float4 z = make_float4(0.f, 0.f, 0.f, 0.f);
    const size_t n4 = ACC_HALVES / 8;
    for (size_t i = tidg; i < n4; i += stride) __stcs(&a[i], z);
}

// Splat one source pixel of warp f. r in [0, NPIX).
static __device__ __forceinline__ void splat_dev(const float* __restrict__ flows,
                                                 const float* __restrict__ im0,
                                                 const float* __restrict__ im1,
                                                 const float* __restrict__ tval,
                                                 int f, unsigned r) {
    const int      b = r >> 20;
    const unsigned p = r & (HWN - 1);
    const int      h = p >> 10;
    const int      w = p & (WW - 1);

    const float t = tval[b];
    const float s = f ? (1.0f / (1.0f - t)) : (1.0f / t);

    const float* fb = flows + ((size_t)(f * BB + b) * 2) * HWN;
    const float X = (float)w + s * __ldcs(&fb[p]);
    const float Y = (float)h + s * __ldcs(&fb[HWN + p]);

    const float x0f = floorf(X), y0f = floorf(Y);
    const int   x0 = (int)x0f,  y0 = (int)y0f;
    const float fx = X - x0f,   fy = Y - y0f;

    if (x0 < -1 || x0 > WW - 1) return;
    if (y0 < -1 || y0 > HH - 1) return;

    const float* im = f ? im1 : im0;
    const float v0 = __ldcs(&im[((size_t)b * CC + 0) * HWN + p]);
    const float v1 = __ldcs(&im[((size_t)b * CC + 1) * HWN + p]);
    const float v2 = __ldcs(&im[((size_t)b * CC + 2) * HWN + p]);

    __half* buf = g_acc[f];
    const bool even = (x0 & 1) == 0;

    #pragma unroll
    for (int rr = 0; rr < 2; rr++) {
        const int y = y0 + rr;
        if ((unsigned)y >= (unsigned)HH) continue;
        const float wy = rr ? fy : (1.0f - fy);
        const float wa = (1.0f - fx) * wy;    // corner x0
        const float wb = fx * wy;             // corner x0+1
        __half* dst = buf + ((size_t)(b * HH + y) * SW + 2 + x0) * 4;
        const unsigned a0 = pack2(wa * v0, wa * v1);
        const unsigned a1 = pack2(wa * v2, 0.0f);
        const unsigned b0 = pack2(wb * v0, wb * v1);
        const unsigned b1 = pack2(wb * v2, 0.0f);
        if (even) {
            red_v4h(dst, a0, a1, b0, b1);
        } else {
            red_v2h(dst, a0, a1);
            red_v2h(dst + 4, b0, b1);
        }
    }
}

// Partial loss for one f: sum |warp_f - ref| (2 px/thread), block-reduce,
// one atomicAdd per block.
static __device__ __forceinline__ void loss_dev(const float* __restrict__ ref,
                                                int f, unsigned rb, unsigned nblk,
                                                float* __restrict__ out) {
    float acc = 0.f;
    const unsigned stride = nblk * TPB;
    for (unsigned i = rb * TPB + threadIdx.x; i < NPAIR; i += stride) {
        const unsigned pp = i << 1;
        const int      b  = pp >> 20;
        const unsigned p  = pp & (HWN - 1);
        const int      y  = p >> 10;
        const int      x  = p & (WW - 1);          // even
        const size_t ai = (((size_t)(b * HH + y)) * SW + 2 + x) * 4;  // 16B aligned

        const uint4 u = __ldcs(reinterpret_cast<const uint4*>(&g_acc[f][ai]));
        const float2 p0a = __half22float2(*reinterpret_cast<const __half2*>(&u.x));
        const float2 p0b = __half22float2(*reinterpret_cast<const __half2*>(&u.y));
        const float2 p1a = __half22float2(*reinterpret_cast<const __half2*>(&u.z));
        const float2 p1b = __half22float2(*reinterpret_cast<const __half2*>(&u.w));

        const size_t base = (size_t)b * CC * HWN + p;
        const float2 r0 = __ldcs(reinterpret_cast<const float2*>(&ref[base]));
        const float2 r1 = __ldcs(reinterpret_cast<const float2*>(&ref[base + HWN]));
        const float2 r2 = __ldcs(reinterpret_cast<const float2*>(&ref[base + 2 * HWN]));

        acc += fabsf(p0a.x - r0.x) + fabsf(p0a.y - r1.x) + fabsf(p0b.x - r2.x);
        acc += fabsf(p1a.x - r0.y) + fabsf(p1a.y - r1.y) + fabsf(p1b.x - r2.y);
    }
    #pragma unroll
    for (int o = 16; o; o >>= 1) acc += __shfl_down_sync(0xffffffffu, acc, o);
    __shared__ float sb[8];
    const int lane = threadIdx.x & 31, wid = threadIdx.x >> 5;
    if (lane == 0) sb[wid] = acc;
    __syncthreads();
    if (wid == 0) {
        acc = (lane < (TPB >> 5)) ? sb[lane] : 0.f;
        #pragma unroll
        for (int o = 16; o; o >>= 1) acc += __shfl_down_sync(0xffffffffu, acc, o);
        if (lane == 0) atomicAdd(out, acc * (1.0f / (float)NELEM));
    }
}

// ---------- kernels ----------

__global__ void __launch_bounds__(TPB) k1_zero0(float* __restrict__ out) {
    zero_f_dev(0, blockIdx.x, gridDim.x);
    if (blockIdx.x == 0 && threadIdx.x == 0) *out = 0.f;
}

__global__ void __launch_bounds__(TPB) k2_zero1_splat0(
        const float* __restrict__ flows, const float* __restrict__ im0,
        const float* __restrict__ im1, const float* __restrict__ tval) {
    if (blockIdx.x < ZBLK) {
        zero_f_dev(1, blockIdx.x, ZBLK);
    } else {
        const unsigned r = (blockIdx.x - ZBLK) * TPB + threadIdx.x;
        splat_dev(flows, im0, im1, tval, 0, r);
    }
}

__global__ void __launch_bounds__(TPB) k3_loss0_splat1(
        const float* __restrict__ flows, const float* __restrict__ im0,
        const float* __restrict__ im1, const float* __restrict__ tval,
        float* __restrict__ out) {
    if (blockIdx.x < LBLK) {
        loss_dev(im1, 0, blockIdx.x, LBLK, out);   // warp0 vs im1
    } else {
        const unsigned r = (blockIdx.x - LBLK) * TPB + threadIdx.x;
        splat_dev(flows, im0, im1, tval, 1, r);
    }
}

__global__ void __launch_bounds__(TPB) k4_loss1(const float* __restrict__ im0,
                                                float* __restrict__ out) {
    loss_dev(im0, 1, blockIdx.x, gridDim.x, out);  // warp1 vs im0
}

extern "C" void kernel_launch(void* const* d_in, const int* in_sizes, int n_in,
                              void* d_out, int out_size) {
    const float* flows = (const float*)d_in[0];   // [2,B,2,H,W]
    const float* im0   = (const float*)d_in[1];   // [B,C,H,W]
    const float* im1   = (const float*)d_in[2];   // [B,C,H,W]
    const float* tval  = (const float*)d_in[3];   // [B]
    float* out = (float*)d_out;

    k1_zero0<<<ZBLK, TPB>>>(out);
    k2_zero1_splat0<<<ZBLK + SPLAT_BLKS, TPB>>>(flows, im0, im1, tval);
    k3_loss0_splat1<<<LBLK + SPLAT_BLKS, TPB>>>(flows, im0, im1, tval, out);
    k4_loss1<<<LBLK, TPB>>>(im0, out);
}